// round 4
// baseline (speedup 1.0000x reference)
#include <cuda_runtime.h>
#include <math.h>
#include <stdint.h>

#define B_  16
#define L_  1024
#define E_  128
#define DI  256
#define DS  48
#define KC  4
#define DTR 8
#define XD  104           // DTR + 2*DS
#define BL  (B_*L_)

// ---------------- scratch ----------------------------------------------------
#define N_CONV   ((size_t)B_*E_*L_)
#define N_HT     ((size_t)BL*E_)
#define N_XZ     ((size_t)BL*2*DI)
#define N_XC     ((size_t)BL*DI)
#define N_XD     ((size_t)BL*XD)

#define OFF_GA   ((size_t)0)
#define OFF_GB   (OFF_GA + N_CONV)
#define OFF_HT   (OFF_GB + N_CONV)
#define OFF_U    (OFF_HT + N_HT)
#define OFF_XZ   (OFF_U + N_HT)
#define OFF_XC0  (OFF_XZ + N_XZ)
#define OFF_XC1  (OFF_XC0 + N_XC)
#define OFF_XD0  (OFF_XC1 + N_XC)
#define OFF_XD1  (OFF_XD0 + N_XD)
#define OFF_Y0   (OFF_XD1 + N_XD)
#define OFF_Y1   (OFF_Y0 + N_XC)
#define SCRATCH_TOTAL (OFF_Y1 + N_XC)

static __device__ float g_scratch[SCRATCH_TOTAL];

// ---------------- helpers ----------------------------------------------------
typedef unsigned long long ull;

__device__ __forceinline__ void fma2(ull& d, ull a, ull b) {
    asm("fma.rn.f32x2 %0, %1, %2, %0;" : "+l"(d) : "l"(a), "l"(b));
}
__device__ __forceinline__ void unpack2(ull v, float& lo, float& hi) {
    asm("mov.b64 {%0, %1}, %2;" : "=f"(lo), "=f"(hi) : "l"(v));
}
__device__ __forceinline__ float ex2f(float x) {
    float r; asm("ex2.approx.f32 %0, %1;" : "=f"(r) : "f"(x)); return r;
}
__device__ __forceinline__ float geluf(float x) {
    return 0.5f * x * (1.0f + erff(x * 0.70710678118654752f));
}
__device__ __forceinline__ float siluf(float x) {
    return x / (1.0f + __expf(-x));
}
__device__ __forceinline__ float softplusf(float x) {
    return fmaxf(x, 0.0f) + log1pf(__expf(-fabsf(x)));
}

// inner product step shared by all tiled kernels: acc[4][4] over 16 kk
#define MMA_STEP(cur)                                                          \
    _Pragma("unroll")                                                          \
    for (int kk = 0; kk < 16; kk++) {                                          \
        ulonglong2 a0 = *(const ulonglong2*)&Xs2[cur][kk][ty * 8];             \
        ulonglong2 a1 = *(const ulonglong2*)&Xs2[cur][kk][ty * 8 + 4];         \
        ulonglong2 b0 = *(const ulonglong2*)&Ws[cur][kk][tx * 8];              \
        ulonglong2 b1 = *(const ulonglong2*)&Ws[cur][kk][tx * 8 + 4];          \
        ull av[4] = {a0.x, a0.y, a1.x, a1.y};                                  \
        ull bv[4] = {b0.x, b0.y, b1.x, b1.y};                                  \
        _Pragma("unroll")                                                      \
        for (int i = 0; i < 4; i++)                                            \
            _Pragma("unroll")                                                  \
            for (int j = 0; j < 4; j++) fma2(acc[i][j], av[i], bv[j]);         \
    }

// ---------------- conv0 (1->128ch, k=5, pad2) + gelu, out [b,e,t] -----------
__global__ void k_conv0g(const float* __restrict__ x, const float* __restrict__ w0,
                         const float* __restrict__ b0, float* __restrict__ out) {
    int idx = blockIdx.x * blockDim.x + threadIdx.x;
    if (idx >= (int)N_CONV) return;
    int t = idx % L_;
    int e = (idx / L_) % E_;
    int b = idx / (L_ * E_);
    float acc = b0[e];
#pragma unroll
    for (int j = 0; j < 5; j++) {
        int ti = t + j - 2;
        if (ti >= 0 && ti < L_) acc += w0[e * 5 + j] * x[b * L_ + ti];
    }
    out[idx] = geluf(acc);
}

// ============================================================================
// Dilated conv 128->128 k=5: 64(t) x 128(o) tile, FFMA2, double-buffered,
// 2 CTAs/SM.  MODE 0: out[b,o,t] = gelu(conv+b).
// MODE 1: ht[b,t,o] = conv+b + x[b,t] + pos[t,o].
// ============================================================================
template <int MODE>
__global__ void __launch_bounds__(256, 2) k_dilconv(
        const float* __restrict__ g, const float* __restrict__ W,
        const float* __restrict__ bias, float* __restrict__ out, int dil,
        const float* __restrict__ x, const float* __restrict__ pos) {
    __shared__ float Xs2[2][16][132];
    __shared__ float Ws[2][16][132];
    int b  = blockIdx.z;
    int t0 = blockIdx.x * 64;
    int tid = threadIdx.x;
    int tx = tid & 15, ty = tid >> 4;
    int rowk = tid >> 4;          // 0..15 (k row for X staging)
    int tc   = (tid & 15) * 4;    // t offset within tile for X staging

    ull acc[4][4];
#pragma unroll
    for (int i = 0; i < 4; i++)
#pragma unroll
        for (int j = 0; j < 4; j++) acc[i][j] = 0ull;

    auto LDX = [&](int k0, float2& v0, float2& v1) {
        int kg = k0 + rowk;
        int ci = kg / 5;
        int j  = kg - ci * 5;
        int tg = t0 + tc + (j - 2) * dil;
        const float* base = g + ((size_t)b * E_ + ci) * L_;
        v0 = (tg >= 0 && tg < L_) ? *(const float2*)&base[tg] : make_float2(0.f, 0.f);
        int tg2 = tg + 2;
        v1 = (tg2 >= 0 && tg2 < L_) ? *(const float2*)&base[tg2] : make_float2(0.f, 0.f);
    };
    auto LDW = [&](int k0, float4 wf[2]) {
#pragma unroll
        for (int p = 0; p < 2; p++) {
            int gid = tid + p * 256;
            int o = gid >> 2, kv = gid & 3;
            wf[p] = *(const float4*)&W[(size_t)o * 640 + k0 + kv * 4];
        }
    };
    auto STX = [&](int s, float2 v0, float2 v1) {
        *(float4*)&Xs2[s][rowk][2 * tc]     = make_float4(v0.x, v0.x, v0.y, v0.y);
        *(float4*)&Xs2[s][rowk][2 * tc + 4] = make_float4(v1.x, v1.x, v1.y, v1.y);
    };
    auto STW = [&](int s, float4 wf[2]) {
#pragma unroll
        for (int p = 0; p < 2; p++) {
            int gid = tid + p * 256;
            int o = gid >> 2, kv = gid & 3;
            Ws[s][kv * 4 + 0][o] = wf[p].x;
            Ws[s][kv * 4 + 1][o] = wf[p].y;
            Ws[s][kv * 4 + 2][o] = wf[p].z;
            Ws[s][kv * 4 + 3][o] = wf[p].w;
        }
    };

    float2 xv0, xv1; float4 wf[2];
    LDX(0, xv0, xv1); LDW(0, wf);
    STX(0, xv0, xv1); STW(0, wf);
    __syncthreads();

    const int NK = 40;
    for (int kt = 0; kt < NK; kt++) {
        int cur = kt & 1;
        float2 nx0, nx1; float4 nwf[2];
        if (kt + 1 < NK) { LDX((kt + 1) * 16, nx0, nx1); LDW((kt + 1) * 16, nwf); }
        MMA_STEP(cur)
        if (kt + 1 < NK) { STX(1 - cur, nx0, nx1); STW(1 - cur, nwf); }
        __syncthreads();
    }

    if (MODE == 0) {
#pragma unroll
        for (int j = 0; j < 4; j++) {
#pragma unroll
            for (int h = 0; h < 2; h++) {
                int o = tx * 8 + 2 * j + h;
                float bv = bias[o];
                float4 v;
                float f0, f1, f2, f3, dummy;
                if (h == 0) { unpack2(acc[0][j], f0, dummy); unpack2(acc[1][j], f1, dummy);
                              unpack2(acc[2][j], f2, dummy); unpack2(acc[3][j], f3, dummy); }
                else        { unpack2(acc[0][j], dummy, f0); unpack2(acc[1][j], dummy, f1);
                              unpack2(acc[2][j], dummy, f2); unpack2(acc[3][j], dummy, f3); }
                v.x = geluf(f0 + bv); v.y = geluf(f1 + bv);
                v.z = geluf(f2 + bv); v.w = geluf(f3 + bv);
                *(float4*)&out[((size_t)b * E_ + o) * L_ + t0 + ty * 4] = v;
            }
        }
    } else {
#pragma unroll
        for (int i = 0; i < 4; i++) {
            int t = t0 + ty * 4 + i;
            float xb = x[b * L_ + t];
#pragma unroll
            for (int q = 0; q < 2; q++) {
                int o = tx * 8 + 4 * q;
                float4 pv = *(const float4*)&pos[(size_t)t * E_ + o];
                float4 bvv = *(const float4*)&bias[o];
                float l0, h0, l1, h1;
                unpack2(acc[i][2 * q], l0, h0); unpack2(acc[i][2 * q + 1], l1, h1);
                float4 v;
                v.x = l0 + bvv.x + xb + pv.x;
                v.y = h0 + bvv.y + xb + pv.y;
                v.z = l1 + bvv.z + xb + pv.z;
                v.w = h1 + bvv.w + xb + pv.w;
                *(float4*)&out[((size_t)(b * L_ + t)) * E_ + o] = v;
            }
        }
    }
}

// ---------------- layernorm (one warp per row, E=128) -----------------------
__global__ void k_ln(const float* __restrict__ in, const float* __restrict__ w,
                     const float* __restrict__ bg, float* __restrict__ out) {
    int row = blockIdx.x * 8 + (threadIdx.x >> 5);
    int lane = threadIdx.x & 31;
    const float* p = in + (size_t)row * E_;
    float v[4];
#pragma unroll
    for (int k = 0; k < 4; k++) v[k] = p[lane + 32 * k];
    float s = v[0] + v[1] + v[2] + v[3];
#pragma unroll
    for (int m = 16; m > 0; m >>= 1) s += __shfl_xor_sync(0xffffffffu, s, m);
    float mu = s * (1.0f / 128.0f);
    float q = 0.0f;
#pragma unroll
    for (int k = 0; k < 4; k++) { float d = v[k] - mu; q += d * d; }
#pragma unroll
    for (int m = 16; m > 0; m >>= 1) q += __shfl_xor_sync(0xffffffffu, q, m);
    float inv = rsqrtf(q * (1.0f / 128.0f) + 1e-5f);
#pragma unroll
    for (int k = 0; k < 4; k++) {
        int e = lane + 32 * k;
        out[(size_t)row * E_ + e] = (v[k] - mu) * inv * w[e] + bg[e];
    }
}

// ============================================================================
// 64x128-tile GEMM, FFMA2, double-buffered, 2 CTAs/SM.
// C[n,m] = X[n,:].W[m,:] (+res)
// ============================================================================
struct GP { const float* X; const float* W; const float* res; float* C; };

__global__ void __launch_bounds__(256, 2) k_gemm64(
        GP pa, GP pb, int ldX, int Kd, int M, int ldC) {
    GP p = blockIdx.z ? pb : pa;
    __shared__ float Xs2[2][16][132];
    __shared__ float Ws[2][16][132];
    int n0 = blockIdx.y * 64, m0 = blockIdx.x * 128;
    int tid = threadIdx.x;
    int tx = tid & 15, ty = tid >> 4;
    int xrow = tid >> 2, xkv = tid & 3;   // X staging: 64 rows x 4 kv

    ull acc[4][4];
#pragma unroll
    for (int i = 0; i < 4; i++)
#pragma unroll
        for (int j = 0; j < 4; j++) acc[i][j] = 0ull;

    auto LDX = [&](int k0, float4& xf) {
        xf = *(const float4*)&p.X[(size_t)(n0 + xrow) * ldX + k0 + xkv * 4];
    };
    auto LDW = [&](int k0, float4 wf[2]) {
#pragma unroll
        for (int pq = 0; pq < 2; pq++) {
            int gid = tid + pq * 256;
            int row = gid >> 2, kv = gid & 3;
            int m = m0 + row;
            wf[pq] = (m < M) ? *(const float4*)&p.W[(size_t)m * Kd + k0 + kv * 4]
                             : make_float4(0.f, 0.f, 0.f, 0.f);
        }
    };
    auto STX = [&](int s, float4 xf) {
        *(float2*)&Xs2[s][xkv * 4 + 0][2 * xrow] = make_float2(xf.x, xf.x);
        *(float2*)&Xs2[s][xkv * 4 + 1][2 * xrow] = make_float2(xf.y, xf.y);
        *(float2*)&Xs2[s][xkv * 4 + 2][2 * xrow] = make_float2(xf.z, xf.z);
        *(float2*)&Xs2[s][xkv * 4 + 3][2 * xrow] = make_float2(xf.w, xf.w);
    };
    auto STW = [&](int s, float4 wf[2]) {
#pragma unroll
        for (int pq = 0; pq < 2; pq++) {
            int gid = tid + pq * 256;
            int row = gid >> 2, kv = gid & 3;
            Ws[s][kv * 4 + 0][row] = wf[pq].x;
            Ws[s][kv * 4 + 1][row] = wf[pq].y;
            Ws[s][kv * 4 + 2][row] = wf[pq].z;
            Ws[s][kv * 4 + 3][row] = wf[pq].w;
        }
    };

    float4 xf, wf[2];
    LDX(0, xf); LDW(0, wf);
    STX(0, xf); STW(0, wf);
    __syncthreads();

    int nk = Kd >> 4;
    for (int kt = 0; kt < nk; kt++) {
        int cur = kt & 1;
        float4 nxf, nwf[2];
        if (kt + 1 < nk) { LDX((kt + 1) * 16, nxf); LDW((kt + 1) * 16, nwf); }
        MMA_STEP(cur)
        if (kt + 1 < nk) { STX(1 - cur, nxf); STW(1 - cur, nwf); }
        __syncthreads();
    }

#pragma unroll
    for (int i = 0; i < 4; i++) {
        int n = n0 + ty * 4 + i;
        float* crow = p.C + (size_t)n * ldC;
        const float* rrow = p.res ? p.res + (size_t)n * ldC : nullptr;
#pragma unroll
        for (int q = 0; q < 2; q++) {
            int m = m0 + tx * 8 + 4 * q;
            if (m + 3 < M) {
                float l0, h0, l1, h1;
                unpack2(acc[i][2 * q], l0, h0); unpack2(acc[i][2 * q + 1], l1, h1);
                float4 v = make_float4(l0, h0, l1, h1);
                if (rrow) {
                    float4 r = *(const float4*)&rrow[m];
                    v.x += r.x; v.y += r.y; v.z += r.z; v.w += r.w;
                }
                *(float4*)&crow[m] = v;
            }
        }
    }
}

// ============================================================================
// out_proj GEMM with fused gate-gather: X[n,k] = (y0[n,k]+y1[flip,k])*silu(z)
// ============================================================================
__global__ void __launch_bounds__(256, 2) k_gemm_out(
        const float* __restrict__ y0, const float* __restrict__ y1,
        const float* __restrict__ xz, const float* __restrict__ W,
        const float* __restrict__ res, float* __restrict__ C) {
    __shared__ float Xs2[2][16][132];
    __shared__ float Ws[2][16][132];
    int n0 = blockIdx.y * 64;
    int tid = threadIdx.x;
    int tx = tid & 15, ty = tid >> 4;
    int xrow = tid >> 2, xkv = tid & 3;

    ull acc[4][4];
#pragma unroll
    for (int i = 0; i < 4; i++)
#pragma unroll
        for (int j = 0; j < 4; j++) acc[i][j] = 0ull;

    int nX = n0 + xrow;
    int bX = nX >> 10, tX = nX & 1023;
    const float* y0r = y0 + (size_t)nX * DI;
    const float* y1r = y1 + ((size_t)(bX * L_ + (L_ - 1 - tX))) * DI;
    const float* zr  = xz + (size_t)nX * (2 * DI) + DI;

    auto LDX = [&](int k0, float4& xf) {
        int k = k0 + xkv * 4;
        float4 a = *(const float4*)&y0r[k];
        float4 c = *(const float4*)&y1r[k];
        float4 z = *(const float4*)&zr[k];
        xf.x = (a.x + c.x) * siluf(z.x);
        xf.y = (a.y + c.y) * siluf(z.y);
        xf.z = (a.z + c.z) * siluf(z.z);
        xf.w = (a.w + c.w) * siluf(z.w);
    };
    auto LDW = [&](int k0, float4 wf[2]) {
#pragma unroll
        for (int pq = 0; pq < 2; pq++) {
            int gid = tid + pq * 256;
            int row = gid >> 2, kv = gid & 3;
            wf[pq] = *(const float4*)&W[(size_t)row * DI + k0 + kv * 4];
        }
    };
    auto STX = [&](int s, float4 xf) {
        *(float2*)&Xs2[s][xkv * 4 + 0][2 * xrow] = make_float2(xf.x, xf.x);
        *(float2*)&Xs2[s][xkv * 4 + 1][2 * xrow] = make_float2(xf.y, xf.y);
        *(float2*)&Xs2[s][xkv * 4 + 2][2 * xrow] = make_float2(xf.z, xf.z);
        *(float2*)&Xs2[s][xkv * 4 + 3][2 * xrow] = make_float2(xf.w, xf.w);
    };
    auto STW = [&](int s, float4 wf[2]) {
#pragma unroll
        for (int pq = 0; pq < 2; pq++) {
            int gid = tid + pq * 256;
            int row = gid >> 2, kv = gid & 3;
            Ws[s][kv * 4 + 0][row] = wf[pq].x;
            Ws[s][kv * 4 + 1][row] = wf[pq].y;
            Ws[s][kv * 4 + 2][row] = wf[pq].z;
            Ws[s][kv * 4 + 3][row] = wf[pq].w;
        }
    };

    float4 xf, wf[2];
    LDX(0, xf); LDW(0, wf);
    STX(0, xf); STW(0, wf);
    __syncthreads();

    const int NK = DI / 16;
    for (int kt = 0; kt < NK; kt++) {
        int cur = kt & 1;
        float4 nxf, nwf[2];
        if (kt + 1 < NK) { LDX((kt + 1) * 16, nxf); LDW((kt + 1) * 16, nwf); }
        MMA_STEP(cur)
        if (kt + 1 < NK) { STX(1 - cur, nxf); STW(1 - cur, nwf); }
        __syncthreads();
    }

#pragma unroll
    for (int i = 0; i < 4; i++) {
        int n = n0 + ty * 4 + i;
        float* crow = C + (size_t)n * E_;
        const float* rrow = res + (size_t)n * E_;
#pragma unroll
        for (int q = 0; q < 2; q++) {
            int m = tx * 8 + 4 * q;
            float l0, h0, l1, h1;
            unpack2(acc[i][2 * q], l0, h0); unpack2(acc[i][2 * q + 1], l1, h1);
            float4 r = *(const float4*)&rrow[m];
            *(float4*)&crow[m] = make_float4(l0 + r.x, h0 + r.y, l1 + r.z, h1 + r.w);
        }
    }
}

// ---------------- depthwise causal conv (K=4) + silu; f/r paired on z -------
struct DWP { const float* cw; const float* cb; float* xc; int flip; };
__global__ void k_dwconv(const float* __restrict__ xz, DWP a, DWP b) {
    DWP p = blockIdx.z ? b : a;
    int idx = blockIdx.x * blockDim.x + threadIdx.x;
    if (idx >= (int)N_XC) return;
    int d = idx % DI;
    int bt = idx / DI;
    int t = bt % L_;
    int bb = bt / L_;
    float acc = p.cb[d];
#pragma unroll
    for (int j = 0; j < KC; j++) {
        int ti = t - 3 + j;
        if (ti >= 0 && ti < L_) {
            int ts = p.flip ? (L_ - 1 - ti) : ti;
            acc += p.cw[d * KC + j] * xz[((size_t)(bb * L_ + ts)) * (2 * DI) + d];
        }
    }
    p.xc[idx] = siluf(acc);
}

// ============================================================================
// selective scan: 8 threads per (b,d), 6 states each; delta fused in staging.
// ============================================================================
struct SCP { const float* xc; const float* xd; const float* dtw; const float* dtb;
             const float* Al; const float* Dp; float* y; };
#define SCT 32
__global__ void __launch_bounds__(256) k_scan(SCP pa, SCP pb) {
    SCP p = blockIdx.z ? pb : pa;
    __shared__ float sB[SCT][DS];
    __shared__ float sC[SCT][DS];
    __shared__ float sDel[SCT][32];
    __shared__ float sX[SCT][32];
    int b = blockIdx.y;
    int dbase = blockIdx.x * 32;
    int tid = threadIdx.x;
    int lane = tid & 31, w = tid >> 5;
    int grp = lane >> 3, sub = lane & 7;
    int d = dbase + w * 4 + grp;
    int di = w * 4 + grp;

    float A[6], h[6];
#pragma unroll
    for (int q = 0; q < 6; q++) {
        A[q] = -expf(p.Al[d * DS + sub * 6 + q]) * 1.4426950408889634f;
        h[q] = 0.0f;
    }
    float Dv = p.Dp[d];

    for (int t0 = 0; t0 < L_; t0 += SCT) {
        __syncthreads();
        for (int i = tid; i < SCT * 96; i += 256) {
            int r = i / 96, c = i - r * 96;
            float v = p.xd[(size_t)(b * L_ + t0 + r) * XD + DTR + c];
            if (c < DS) sB[r][c] = v; else sC[r][c - DS] = v;
        }
        for (int i = tid; i < SCT * 32; i += 256) {
            int r = i >> 5, c = i & 31;
            int dg = dbase + c;
            const float* row = p.xd + (size_t)(b * L_ + t0 + r) * XD;
            float acc = p.dtb[dg];
#pragma unroll
            for (int q = 0; q < DTR; q++) acc += row[q] * p.dtw[dg * DTR + q];
            sDel[r][c] = softplusf(acc);
            sX[r][c] = p.xc[(size_t)(b * L_ + t0 + r) * DI + dg];
        }
        __syncthreads();
#pragma unroll 4
        for (int tt = 0; tt < SCT; tt++) {
            float dv = sDel[tt][di], xv = sX[tt][di];
            float dx = dv * xv;
            const float2* Bp = (const float2*)&sB[tt][sub * 6];
            const float2* Cp = (const float2*)&sC[tt][sub * 6];
            float2 B0 = Bp[0], B1 = Bp[1], B2 = Bp[2];
            float2 C0 = Cp[0], C1 = Cp[1], C2 = Cp[2];
            float pr = 0.0f;
            h[0] = ex2f(dv * A[0]) * h[0] + dx * B0.x; pr = fmaf(h[0], C0.x, pr);
            h[1] = ex2f(dv * A[1]) * h[1] + dx * B0.y; pr = fmaf(h[1], C0.y, pr);
            h[2] = ex2f(dv * A[2]) * h[2] + dx * B1.x; pr = fmaf(h[2], C1.x, pr);
            h[3] = ex2f(dv * A[3]) * h[3] + dx * B1.y; pr = fmaf(h[3], C1.y, pr);
            h[4] = ex2f(dv * A[4]) * h[4] + dx * B2.x; pr = fmaf(h[4], C2.x, pr);
            h[5] = ex2f(dv * A[5]) * h[5] + dx * B2.y; pr = fmaf(h[5], C2.y, pr);
            pr += __shfl_xor_sync(0xffffffffu, pr, 1);
            pr += __shfl_xor_sync(0xffffffffu, pr, 2);
            pr += __shfl_xor_sync(0xffffffffu, pr, 4);
            if (sub == 0)
                p.y[(size_t)(b * L_ + t0 + tt) * DI + d] = pr + xv * Dv;
        }
    }
}

// ---------------- launcher --------------------------------------------------
extern "C" void kernel_launch(void* const* d_in, const int* in_sizes, int n_in,
                              void* d_out, int out_size) {
    const float* x     = (const float*)d_in[0];
    const float* cw0   = (const float*)d_in[1];
    const float* cb0   = (const float*)d_in[2];
    const float* convw = (const float*)d_in[3];
    const float* convb = (const float*)d_in[4];
    const float* pos   = (const float*)d_in[5];
    const float* lnw   = (const float*)d_in[6];
    const float* lnb   = (const float*)d_in[7];
    const float* ipw   = (const float*)d_in[8];
    const float* opw   = (const float*)d_in[9];
    const float* cw_f  = (const float*)d_in[10];
    const float* cb_f  = (const float*)d_in[11];
    const float* xp_f  = (const float*)d_in[12];
    const float* dtw_f = (const float*)d_in[13];
    const float* dtb_f = (const float*)d_in[14];
    const float* Al_f  = (const float*)d_in[15];
    const float* D_f   = (const float*)d_in[16];
    const float* cw_r  = (const float*)d_in[17];
    const float* cb_r  = (const float*)d_in[18];
    const float* xp_r  = (const float*)d_in[19];
    const float* dtw_r = (const float*)d_in[20];
    const float* dtb_r = (const float*)d_in[21];
    const float* Al_r  = (const float*)d_in[22];
    const float* D_r   = (const float*)d_in[23];
    float* out = (float*)d_out;

    float* S = nullptr;
    cudaGetSymbolAddress((void**)&S, g_scratch);
    float* gA  = S + OFF_GA;
    float* gB  = S + OFF_GB;
    float* ht  = S + OFF_HT;
    float* u   = S + OFF_U;
    float* xz  = S + OFF_XZ;
    float* xc0 = S + OFF_XC0;
    float* xc1 = S + OFF_XC1;
    float* xd0 = S + OFF_XD0;
    float* xd1 = S + OFF_XD1;
    float* y0  = S + OFF_Y0;
    float* y1  = S + OFF_Y1;

    const int TPB = 256;
    int gXC = (int)((N_XC + TPB - 1) / TPB);
    dim3 gdc(L_ / 64, 1, B_);   // 16 x 16 = 256 blocks

    k_conv0g<<<(int)(N_CONV / TPB), TPB>>>(x, cw0, cb0, gA);
    k_dilconv<0><<<gdc, TPB>>>(gA, convw + 0 * 81920, convb + 0,   gB, 2,  nullptr, nullptr);
    k_dilconv<0><<<gdc, TPB>>>(gB, convw + 1 * 81920, convb + 128, gA, 4,  nullptr, nullptr);
    k_dilconv<0><<<gdc, TPB>>>(gA, convw + 2 * 81920, convb + 256, gB, 8,  nullptr, nullptr);
    k_dilconv<1><<<gdc, TPB>>>(gB, convw + 3 * 81920, convb + 384, ht, 16, x, pos);

    for (int blk = 0; blk < 2; blk++) {
        k_ln<<<BL / 8, TPB>>>(ht, lnw + blk * E_, lnb + blk * E_, u);

        GP ip{u, ipw + (size_t)blk * 2 * DI * E_, nullptr, xz};
        k_gemm64<<<dim3(4, BL / 64, 1), TPB>>>(ip, ip, E_, E_, 2 * DI, 2 * DI);

        DWP dwa{cw_f + blk * DI * KC, cb_f + blk * DI, xc0, 0};
        DWP dwb{cw_r + blk * DI * KC, cb_r + blk * DI, xc1, 1};
        k_dwconv<<<dim3(gXC, 1, 2), TPB>>>(xz, dwa, dwb);

        GP xa{xc0, xp_f + (size_t)blk * XD * DI, nullptr, xd0};
        GP xb{xc1, xp_r + (size_t)blk * XD * DI, nullptr, xd1};
        k_gemm64<<<dim3(1, BL / 64, 2), TPB>>>(xa, xb, DI, DI, XD, XD);

        SCP sa{xc0, xd0, dtw_f + blk * DI * DTR, dtb_f + blk * DI,
               Al_f + (size_t)blk * DI * DS, D_f + blk * DI, y0};
        SCP sb{xc1, xd1, dtw_r + blk * DI * DTR, dtb_r + blk * DI,
               Al_r + (size_t)blk * DI * DS, D_r + blk * DI, y1};
        k_scan<<<dim3(DI / 32, B_, 2), TPB>>>(sa, sb);

        float* dst = (blk == 1) ? out : ht;
        k_gemm_out<<<dim3(1, BL / 64, 1), TPB>>>(
            y0, y1, xz, opw + (size_t)blk * E_ * DI, ht, dst);
    }
}

// round 5
// speedup vs baseline: 1.4150x; 1.4150x over previous
#include <cuda_runtime.h>
#include <math.h>
#include <stdint.h>

#define B_  16
#define L_  1024
#define E_  128
#define DI  256
#define DS  48
#define KC  4
#define DTR 8
#define XD  104           // DTR + 2*DS
#define BL  (B_*L_)

// ---------------- scratch ----------------------------------------------------
#define N_CONV   ((size_t)B_*E_*L_)
#define N_HT     ((size_t)BL*E_)
#define N_XZ     ((size_t)BL*2*DI)
#define N_XC     ((size_t)BL*DI)
#define N_XD     ((size_t)BL*XD)

#define OFF_GA   ((size_t)0)
#define OFF_GB   (OFF_GA + N_CONV)
#define OFF_HT   (OFF_GB + N_CONV)
#define OFF_U    (OFF_HT + N_HT)
#define OFF_XZ   (OFF_U + N_HT)
#define OFF_XC0  (OFF_XZ + N_XZ)
#define OFF_XC1  (OFF_XC0 + N_XC)
#define OFF_XD0  (OFF_XC1 + N_XC)
#define OFF_XD1  (OFF_XD0 + N_XD)
#define OFF_Y0   (OFF_XD1 + N_XD)
#define OFF_Y1   (OFF_Y0 + N_XC)
#define SCRATCH_TOTAL (OFF_Y1 + N_XC)

static __device__ float g_scratch[SCRATCH_TOTAL];

// ---------------- helpers ----------------------------------------------------
typedef unsigned long long ull;

__device__ __forceinline__ void fma2(ull& d, ull a, ull b) {
    asm("fma.rn.f32x2 %0, %1, %2, %0;" : "+l"(d) : "l"(a), "l"(b));
}
__device__ __forceinline__ void unpack2(ull v, float& lo, float& hi) {
    asm("mov.b64 {%0, %1}, %2;" : "=f"(lo), "=f"(hi) : "l"(v));
}
__device__ __forceinline__ ull dup2(float x) {
    ull r; asm("mov.b64 %0, {%1, %1};" : "=l"(r) : "f"(x)); return r;
}
__device__ __forceinline__ float ex2f(float x) {
    float r; asm("ex2.approx.f32 %0, %1;" : "=f"(r) : "f"(x)); return r;
}
__device__ __forceinline__ float geluf(float x) {
    return 0.5f * x * (1.0f + erff(x * 0.70710678118654752f));
}
__device__ __forceinline__ float siluf(float x) {
    return x / (1.0f + __expf(-x));
}
__device__ __forceinline__ float softplusf(float x) {
    return fmaxf(x, 0.0f) + log1pf(__expf(-fabsf(x)));
}

// MMA inner step: acc[8][4], pairs over n.  A: 4x LDS.128 broadcast (same ty
// across warp).  B: 1x LDS.128 per thread (4 m floats), reg-duplicated.
#define MMA_STEP(cur)                                                          \
    _Pragma("unroll")                                                          \
    for (int kk = 0; kk < 16; kk++) {                                          \
        const ulonglong2* ap = (const ulonglong2*)&Xs[cur][kk][ty * 16];       \
        ulonglong2 A0 = ap[0], A1 = ap[1], A2 = ap[2], A3 = ap[3];             \
        float4 w4 = *(const float4*)&Ws[cur][kk][tx * 4];                      \
        ull av[8] = {A0.x, A0.y, A1.x, A1.y, A2.x, A2.y, A3.x, A3.y};          \
        ull bv[4] = {dup2(w4.x), dup2(w4.y), dup2(w4.z), dup2(w4.w)};          \
        _Pragma("unroll")                                                      \
        for (int i = 0; i < 8; i++)                                            \
            _Pragma("unroll")                                                  \
            for (int j = 0; j < 4; j++) fma2(acc[i][j], av[i], bv[j]);         \
    }

// ---------------- conv0 (1->128ch, k=5, pad2) + gelu, out [b,e,t] -----------
__global__ void k_conv0g(const float* __restrict__ x, const float* __restrict__ w0,
                         const float* __restrict__ b0, float* __restrict__ out) {
    int idx = blockIdx.x * blockDim.x + threadIdx.x;
    if (idx >= (int)N_CONV) return;
    int t = idx % L_;
    int e = (idx / L_) % E_;
    int b = idx / (L_ * E_);
    float acc = b0[e];
#pragma unroll
    for (int j = 0; j < 5; j++) {
        int ti = t + j - 2;
        if (ti >= 0 && ti < L_) acc += w0[e * 5 + j] * x[b * L_ + ti];
    }
    out[idx] = geluf(acc);
}

// ============================================================================
// Dilated conv 128->128 k=5: 128(t) x 128(o) tile.
// MODE 0: out[b,o,t] = gelu(conv+b).  MODE 1: ht[b,t,o] = conv+b+x+pos.
// ============================================================================
template <int MODE>
__global__ void __launch_bounds__(256) k_dilconv(
        const float* __restrict__ g, const float* __restrict__ W,
        const float* __restrict__ bias, float* __restrict__ out, int dil,
        const float* __restrict__ x, const float* __restrict__ pos) {
    __shared__ __align__(16) float Xs[2][16][132];
    __shared__ __align__(16) float Ws[2][16][132];
    int b  = blockIdx.z;
    int t0 = blockIdx.x * 128;
    int tid = threadIdx.x;
    int tx = tid & 31, ty = tid >> 5;          // tx: 4 o each; ty: 16 t each
    int rowk = tid >> 4;                        // 0..15 X-staging row
    int tcol = (tid & 15) * 8;                  // X-staging t offset
    int wrow = tid >> 1;                        // 0..127 W-staging o row
    int whalf = tid & 1;                        // 8 k floats each

    ull acc[8][4];
#pragma unroll
    for (int i = 0; i < 8; i++)
#pragma unroll
        for (int j = 0; j < 4; j++) acc[i][j] = 0ull;

    auto LDX = [&](int k0, float v[8]) {
        int kg = k0 + rowk;
        int ci = kg / 5;
        int j  = kg - ci * 5;
        int tg = t0 + tcol + (j - 2) * dil;
        const float* base = g + ((size_t)b * E_ + ci) * L_;
        if (tg >= 0 && tg + 7 < L_) {
            float2 a = *(const float2*)&base[tg];
            float2 c = *(const float2*)&base[tg + 2];
            float2 d = *(const float2*)&base[tg + 4];
            float2 e = *(const float2*)&base[tg + 6];
            v[0] = a.x; v[1] = a.y; v[2] = c.x; v[3] = c.y;
            v[4] = d.x; v[5] = d.y; v[6] = e.x; v[7] = e.y;
        } else {
#pragma unroll
            for (int e2 = 0; e2 < 8; e2++) {
                int tt = tg + e2;
                v[e2] = (tt >= 0 && tt < L_) ? base[tt] : 0.0f;
            }
        }
    };
    auto LDW = [&](int k0, float4 wf[2]) {
        const float* wp = &W[(size_t)wrow * 640 + k0 + whalf * 8];
        wf[0] = *(const float4*)&wp[0];
        wf[1] = *(const float4*)&wp[4];
    };
    auto STX = [&](int s, float v[8]) {
        *(float4*)&Xs[s][rowk][tcol]     = make_float4(v[0], v[1], v[2], v[3]);
        *(float4*)&Xs[s][rowk][tcol + 4] = make_float4(v[4], v[5], v[6], v[7]);
    };
    auto STW = [&](int s, float4 wf[2]) {
        Ws[s][whalf * 8 + 0][wrow] = wf[0].x;
        Ws[s][whalf * 8 + 1][wrow] = wf[0].y;
        Ws[s][whalf * 8 + 2][wrow] = wf[0].z;
        Ws[s][whalf * 8 + 3][wrow] = wf[0].w;
        Ws[s][whalf * 8 + 4][wrow] = wf[1].x;
        Ws[s][whalf * 8 + 5][wrow] = wf[1].y;
        Ws[s][whalf * 8 + 6][wrow] = wf[1].z;
        Ws[s][whalf * 8 + 7][wrow] = wf[1].w;
    };

    float xv[8]; float4 wf[2];
    LDX(0, xv); LDW(0, wf);
    STX(0, xv); STW(0, wf);
    __syncthreads();

    const int NK = 40;
    for (int kt = 0; kt < NK; kt++) {
        int cur = kt & 1;
        float nxv[8]; float4 nwf[2];
        if (kt + 1 < NK) { LDX((kt + 1) * 16, nxv); LDW((kt + 1) * 16, nwf); }
        MMA_STEP(cur)
        if (kt + 1 < NK) { STX(1 - cur, nxv); STW(1 - cur, nwf); }
        __syncthreads();
    }

    if (MODE == 0) {
        // out[b,o,t], acc[i][j] = (c[t+2i? ->], pair over t)
#pragma unroll
        for (int i = 0; i < 8; i++) {
            int t = t0 + ty * 16 + 2 * i;
#pragma unroll
            for (int j = 0; j < 4; j++) {
                int o = tx * 4 + j;
                float lo, hi; unpack2(acc[i][j], lo, hi);
                float bv = bias[o];
                float2 v = make_float2(geluf(lo + bv), geluf(hi + bv));
                *(float2*)&out[((size_t)b * E_ + o) * L_ + t] = v;
            }
        }
    } else {
#pragma unroll
        for (int i = 0; i < 8; i++) {
            int t = t0 + ty * 16 + 2 * i;
            float lo[4], hi[4];
#pragma unroll
            for (int j = 0; j < 4; j++) unpack2(acc[i][j], lo[j], hi[j]);
            int o = tx * 4;
            float4 bv = *(const float4*)&bias[o];
#pragma unroll
            for (int h = 0; h < 2; h++) {
                int tt = t + h;
                float xb = x[b * L_ + tt];
                float4 pv = *(const float4*)&pos[(size_t)tt * E_ + o];
                const float* f = h ? hi : lo;
                float4 v = make_float4(f[0] + bv.x + xb + pv.x,
                                       f[1] + bv.y + xb + pv.y,
                                       f[2] + bv.z + xb + pv.z,
                                       f[3] + bv.w + xb + pv.w);
                *(float4*)&out[((size_t)(b * L_ + tt)) * E_ + o] = v;
            }
        }
    }
}

// ---------------- layernorm (one warp per row, E=128) -----------------------
__global__ void k_ln(const float* __restrict__ in, const float* __restrict__ w,
                     const float* __restrict__ bg, float* __restrict__ out) {
    int row = blockIdx.x * 8 + (threadIdx.x >> 5);
    int lane = threadIdx.x & 31;
    const float* p = in + (size_t)row * E_;
    float v[4];
#pragma unroll
    for (int k = 0; k < 4; k++) v[k] = p[lane + 32 * k];
    float s = v[0] + v[1] + v[2] + v[3];
#pragma unroll
    for (int m = 16; m > 0; m >>= 1) s += __shfl_xor_sync(0xffffffffu, s, m);
    float mu = s * (1.0f / 128.0f);
    float q = 0.0f;
#pragma unroll
    for (int k = 0; k < 4; k++) { float d = v[k] - mu; q += d * d; }
#pragma unroll
    for (int m = 16; m > 0; m >>= 1) q += __shfl_xor_sync(0xffffffffu, q, m);
    float inv = rsqrtf(q * (1.0f / 128.0f) + 1e-5f);
#pragma unroll
    for (int k = 0; k < 4; k++) {
        int e = lane + 32 * k;
        out[(size_t)row * E_ + e] = (v[k] - mu) * inv * w[e] + bg[e];
    }
}

// ============================================================================
// 128x128-tile GEMM.  C[n,m] = X[n,:].W[m,:] (+res).  f/r paired on z.
// ============================================================================
struct GP { const float* X; const float* W; const float* res; float* C; };

__global__ void __launch_bounds__(256, 2) k_gemm(
        GP pa, GP pb, int ldX, int Kd, int M, int ldC) {
    GP p = blockIdx.z ? pb : pa;
    __shared__ __align__(16) float Xs[2][16][132];
    __shared__ __align__(16) float Ws[2][16][132];
    int n0 = blockIdx.y * 128, m0 = blockIdx.x * 128;
    int tid = threadIdx.x;
    int tx = tid & 31, ty = tid >> 5;
    int row = tid >> 1;        // staging row (n or m), 0..127
    int half = tid & 1;        // 8 k floats each

    ull acc[8][4];
#pragma unroll
    for (int i = 0; i < 8; i++)
#pragma unroll
        for (int j = 0; j < 4; j++) acc[i][j] = 0ull;

    auto LDX = [&](int k0, float4 xf[2]) {
        const float* xp = &p.X[(size_t)(n0 + row) * ldX + k0 + half * 8];
        xf[0] = *(const float4*)&xp[0];
        xf[1] = *(const float4*)&xp[4];
    };
    auto LDW = [&](int k0, float4 wf[2]) {
        int m = m0 + row;
        if (m < M) {
            const float* wp = &p.W[(size_t)m * Kd + k0 + half * 8];
            wf[0] = *(const float4*)&wp[0];
            wf[1] = *(const float4*)&wp[4];
        } else {
            wf[0] = wf[1] = make_float4(0.f, 0.f, 0.f, 0.f);
        }
    };
    auto STX = [&](int s, float4 xf[2]) {
        Xs[s][half * 8 + 0][row] = xf[0].x;
        Xs[s][half * 8 + 1][row] = xf[0].y;
        Xs[s][half * 8 + 2][row] = xf[0].z;
        Xs[s][half * 8 + 3][row] = xf[0].w;
        Xs[s][half * 8 + 4][row] = xf[1].x;
        Xs[s][half * 8 + 5][row] = xf[1].y;
        Xs[s][half * 8 + 6][row] = xf[1].z;
        Xs[s][half * 8 + 7][row] = xf[1].w;
    };
    auto STW = [&](int s, float4 wf[2]) {
        Ws[s][half * 8 + 0][row] = wf[0].x;
        Ws[s][half * 8 + 1][row] = wf[0].y;
        Ws[s][half * 8 + 2][row] = wf[0].z;
        Ws[s][half * 8 + 3][row] = wf[0].w;
        Ws[s][half * 8 + 4][row] = wf[1].x;
        Ws[s][half * 8 + 5][row] = wf[1].y;
        Ws[s][half * 8 + 6][row] = wf[1].z;
        Ws[s][half * 8 + 7][row] = wf[1].w;
    };

    float4 xf[2], wf[2];
    LDX(0, xf); LDW(0, wf);
    STX(0, xf); STW(0, wf);
    __syncthreads();

    int nk = Kd >> 4;
    for (int kt = 0; kt < nk; kt++) {
        int cur = kt & 1;
        float4 nxf[2], nwf[2];
        if (kt + 1 < nk) { LDX((kt + 1) * 16, nxf); LDW((kt + 1) * 16, nwf); }
        MMA_STEP(cur)
        if (kt + 1 < nk) { STX(1 - cur, nxf); STW(1 - cur, nwf); }
        __syncthreads();
    }

#pragma unroll
    for (int i = 0; i < 8; i++) {
        int n = n0 + ty * 16 + 2 * i;
        float lo[4], hi[4];
#pragma unroll
        for (int j = 0; j < 4; j++) unpack2(acc[i][j], lo[j], hi[j]);
        int m = m0 + tx * 4;
        if (m + 3 < M) {
#pragma unroll
            for (int h = 0; h < 2; h++) {
                int nn = n + h;
                const float* f = h ? hi : lo;
                float4 v = make_float4(f[0], f[1], f[2], f[3]);
                if (p.res) {
                    float4 r = *(const float4*)&p.res[(size_t)nn * ldC + m];
                    v.x += r.x; v.y += r.y; v.z += r.z; v.w += r.w;
                }
                *(float4*)&p.C[(size_t)nn * ldC + m] = v;
            }
        }
    }
}

// ============================================================================
// out_proj GEMM with fused gate-gather: X[n,k] = (y0[n,k]+y1[flip,k])*silu(z)
// ============================================================================
__global__ void __launch_bounds__(256) k_gemm_out(
        const float* __restrict__ y0, const float* __restrict__ y1,
        const float* __restrict__ xz, const float* __restrict__ W,
        const float* __restrict__ res, float* __restrict__ C) {
    __shared__ __align__(16) float Xs[2][16][132];
    __shared__ __align__(16) float Ws[2][16][132];
    int n0 = blockIdx.y * 128;
    int tid = threadIdx.x;
    int tx = tid & 31, ty = tid >> 5;
    int row = tid >> 1;
    int half = tid & 1;

    ull acc[8][4];
#pragma unroll
    for (int i = 0; i < 8; i++)
#pragma unroll
        for (int j = 0; j < 4; j++) acc[i][j] = 0ull;

    int nX = n0 + row;
    int bX = nX >> 10, tX = nX & 1023;
    const float* y0r = y0 + (size_t)nX * DI;
    const float* y1r = y1 + ((size_t)(bX * L_ + (L_ - 1 - tX))) * DI;
    const float* zr  = xz + (size_t)nX * (2 * DI) + DI;

    auto LDX = [&](int k0, float4 xf[2]) {
#pragma unroll
        for (int q = 0; q < 2; q++) {
            int k = k0 + half * 8 + q * 4;
            float4 a = *(const float4*)&y0r[k];
            float4 c = *(const float4*)&y1r[k];
            float4 z = *(const float4*)&zr[k];
            xf[q].x = (a.x + c.x) * siluf(z.x);
            xf[q].y = (a.y + c.y) * siluf(z.y);
            xf[q].z = (a.z + c.z) * siluf(z.z);
            xf[q].w = (a.w + c.w) * siluf(z.w);
        }
    };
    auto LDW = [&](int k0, float4 wf[2]) {
        const float* wp = &W[(size_t)row * DI + k0 + half * 8];
        wf[0] = *(const float4*)&wp[0];
        wf[1] = *(const float4*)&wp[4];
    };
    auto STX = [&](int s, float4 xf[2]) {
#pragma unroll
        for (int q = 0; q < 2; q++) {
            Xs[s][half * 8 + q * 4 + 0][row] = xf[q].x;
            Xs[s][half * 8 + q * 4 + 1][row] = xf[q].y;
            Xs[s][half * 8 + q * 4 + 2][row] = xf[q].z;
            Xs[s][half * 8 + q * 4 + 3][row] = xf[q].w;
        }
    };
    auto STW = [&](int s, float4 wf[2]) {
#pragma unroll
        for (int q = 0; q < 2; q++) {
            Ws[s][half * 8 + q * 4 + 0][row] = wf[q].x;
            Ws[s][half * 8 + q * 4 + 1][row] = wf[q].y;
            Ws[s][half * 8 + q * 4 + 2][row] = wf[q].z;
            Ws[s][half * 8 + q * 4 + 3][row] = wf[q].w;
        }
    };

    float4 xf[2], wf[2];
    LDX(0, xf); LDW(0, wf);
    STX(0, xf); STW(0, wf);
    __syncthreads();

    const int NK = DI / 16;
    for (int kt = 0; kt < NK; kt++) {
        int cur = kt & 1;
        float4 nxf[2], nwf[2];
        if (kt + 1 < NK) { LDX((kt + 1) * 16, nxf); LDW((kt + 1) * 16, nwf); }
        MMA_STEP(cur)
        if (kt + 1 < NK) { STX(1 - cur, nxf); STW(1 - cur, nwf); }
        __syncthreads();
    }

#pragma unroll
    for (int i = 0; i < 8; i++) {
        int n = n0 + ty * 16 + 2 * i;
        float lo[4], hi[4];
#pragma unroll
        for (int j = 0; j < 4; j++) unpack2(acc[i][j], lo[j], hi[j]);
        int m = tx * 4;
#pragma unroll
        for (int h = 0; h < 2; h++) {
            int nn = n + h;
            const float* f = h ? hi : lo;
            float4 r = *(const float4*)&res[(size_t)nn * E_ + m];
            *(float4*)&C[(size_t)nn * E_ + m] =
                make_float4(f[0] + r.x, f[1] + r.y, f[2] + r.z, f[3] + r.w);
        }
    }
}

// ---------------- depthwise causal conv (K=4) + silu; f/r paired on z -------
struct DWP { const float* cw; const float* cb; float* xc; int flip; };
__global__ void k_dwconv(const float* __restrict__ xz, DWP a, DWP b) {
    DWP p = blockIdx.z ? b : a;
    int idx = blockIdx.x * blockDim.x + threadIdx.x;
    if (idx >= (int)N_XC) return;
    int d = idx % DI;
    int bt = idx / DI;
    int t = bt % L_;
    int bb = bt / L_;
    float acc = p.cb[d];
#pragma unroll
    for (int j = 0; j < KC; j++) {
        int ti = t - 3 + j;
        if (ti >= 0 && ti < L_) {
            int ts = p.flip ? (L_ - 1 - ti) : ti;
            acc += p.cw[d * KC + j] * xz[((size_t)(bb * L_ + ts)) * (2 * DI) + d];
        }
    }
    p.xc[idx] = siluf(acc);
}

// ============================================================================
// selective scan: 8 threads per (b,d), 6 states each; delta fused in staging.
// ============================================================================
struct SCP { const float* xc; const float* xd; const float* dtw; const float* dtb;
             const float* Al; const float* Dp; float* y; };
#define SCT 32
__global__ void __launch_bounds__(256) k_scan(SCP pa, SCP pb) {
    SCP p = blockIdx.z ? pb : pa;
    __shared__ float sB[SCT][DS];
    __shared__ float sC[SCT][DS];
    __shared__ float sDel[SCT][32];
    __shared__ float sX[SCT][32];
    int b = blockIdx.y;
    int dbase = blockIdx.x * 32;
    int tid = threadIdx.x;
    int lane = tid & 31, w = tid >> 5;
    int grp = lane >> 3, sub = lane & 7;
    int d = dbase + w * 4 + grp;
    int di = w * 4 + grp;

    float A[6], h[6];
#pragma unroll
    for (int q = 0; q < 6; q++) {
        A[q] = -expf(p.Al[d * DS + sub * 6 + q]) * 1.4426950408889634f;
        h[q] = 0.0f;
    }
    float Dv = p.Dp[d];

    for (int t0 = 0; t0 < L_; t0 += SCT) {
        __syncthreads();
        for (int i = tid; i < SCT * 96; i += 256) {
            int r = i / 96, c = i - r * 96;
            float v = p.xd[(size_t)(b * L_ + t0 + r) * XD + DTR + c];
            if (c < DS) sB[r][c] = v; else sC[r][c - DS] = v;
        }
        for (int i = tid; i < SCT * 32; i += 256) {
            int r = i >> 5, c = i & 31;
            int dg = dbase + c;
            const float* row = p.xd + (size_t)(b * L_ + t0 + r) * XD;
            float acc = p.dtb[dg];
#pragma unroll
            for (int q = 0; q < DTR; q++) acc += row[q] * p.dtw[dg * DTR + q];
            sDel[r][c] = softplusf(acc);
            sX[r][c] = p.xc[(size_t)(b * L_ + t0 + r) * DI + dg];
        }
        __syncthreads();
#pragma unroll 4
        for (int tt = 0; tt < SCT; tt++) {
            float dv = sDel[tt][di], xv = sX[tt][di];
            float dx = dv * xv;
            const float2* Bp = (const float2*)&sB[tt][sub * 6];
            const float2* Cp = (const float2*)&sC[tt][sub * 6];
            float2 B0 = Bp[0], B1 = Bp[1], B2 = Bp[2];
            float2 C0 = Cp[0], C1 = Cp[1], C2 = Cp[2];
            float pr = 0.0f;
            h[0] = ex2f(dv * A[0]) * h[0] + dx * B0.x; pr = fmaf(h[0], C0.x, pr);
            h[1] = ex2f(dv * A[1]) * h[1] + dx * B0.y; pr = fmaf(h[1], C0.y, pr);
            h[2] = ex2f(dv * A[2]) * h[2] + dx * B1.x; pr = fmaf(h[2], C1.x, pr);
            h[3] = ex2f(dv * A[3]) * h[3] + dx * B1.y; pr = fmaf(h[3], C1.y, pr);
            h[4] = ex2f(dv * A[4]) * h[4] + dx * B2.x; pr = fmaf(h[4], C2.x, pr);
            h[5] = ex2f(dv * A[5]) * h[5] + dx * B2.y; pr = fmaf(h[5], C2.y, pr);
            pr += __shfl_xor_sync(0xffffffffu, pr, 1);
            pr += __shfl_xor_sync(0xffffffffu, pr, 2);
            pr += __shfl_xor_sync(0xffffffffu, pr, 4);
            if (sub == 0)
                p.y[(size_t)(b * L_ + t0 + tt) * DI + d] = pr + xv * Dv;
        }
    }
}

// ---------------- launcher --------------------------------------------------
extern "C" void kernel_launch(void* const* d_in, const int* in_sizes, int n_in,
                              void* d_out, int out_size) {
    const float* x     = (const float*)d_in[0];
    const float* cw0   = (const float*)d_in[1];
    const float* cb0   = (const float*)d_in[2];
    const float* convw = (const float*)d_in[3];
    const float* convb = (const float*)d_in[4];
    const float* pos   = (const float*)d_in[5];
    const float* lnw   = (const float*)d_in[6];
    const float* lnb   = (const float*)d_in[7];
    const float* ipw   = (const float*)d_in[8];
    const float* opw   = (const float*)d_in[9];
    const float* cw_f  = (const float*)d_in[10];
    const float* cb_f  = (const float*)d_in[11];
    const float* xp_f  = (const float*)d_in[12];
    const float* dtw_f = (const float*)d_in[13];
    const float* dtb_f = (const float*)d_in[14];
    const float* Al_f  = (const float*)d_in[15];
    const float* D_f   = (const float*)d_in[16];
    const float* cw_r  = (const float*)d_in[17];
    const float* cb_r  = (const float*)d_in[18];
    const float* xp_r  = (const float*)d_in[19];
    const float* dtw_r = (const float*)d_in[20];
    const float* dtb_r = (const float*)d_in[21];
    const float* Al_r  = (const float*)d_in[22];
    const float* D_r   = (const float*)d_in[23];
    float* out = (float*)d_out;

    float* S = nullptr;
    cudaGetSymbolAddress((void**)&S, g_scratch);
    float* gA  = S + OFF_GA;
    float* gB  = S + OFF_GB;
    float* ht  = S + OFF_HT;
    float* u   = S + OFF_U;
    float* xz  = S + OFF_XZ;
    float* xc0 = S + OFF_XC0;
    float* xc1 = S + OFF_XC1;
    float* xd0 = S + OFF_XD0;
    float* xd1 = S + OFF_XD1;
    float* y0  = S + OFF_Y0;
    float* y1  = S + OFF_Y1;

    const int TPB = 256;
    int gXC = (int)((N_XC + TPB - 1) / TPB);
    dim3 gdc(L_ / 128, 1, B_);   // 8 x 16 = 128 blocks

    k_conv0g<<<(int)(N_CONV / TPB), TPB>>>(x, cw0, cb0, gA);
    k_dilconv<0><<<gdc, TPB>>>(gA, convw + 0 * 81920, convb + 0,   gB, 2,  nullptr, nullptr);
    k_dilconv<0><<<gdc, TPB>>>(gB, convw + 1 * 81920, convb + 128, gA, 4,  nullptr, nullptr);
    k_dilconv<0><<<gdc, TPB>>>(gA, convw + 2 * 81920, convb + 256, gB, 8,  nullptr, nullptr);
    k_dilconv<1><<<gdc, TPB>>>(gB, convw + 3 * 81920, convb + 384, ht, 16, x, pos);

    for (int blk = 0; blk < 2; blk++) {
        k_ln<<<BL / 8, TPB>>>(ht, lnw + blk * E_, lnb + blk * E_, u);

        GP ip{u, ipw + (size_t)blk * 2 * DI * E_, nullptr, xz};
        k_gemm<<<dim3(4, BL / 128, 1), TPB>>>(ip, ip, E_, E_, 2 * DI, 2 * DI);

        DWP dwa{cw_f + blk * DI * KC, cb_f + blk * DI, xc0, 0};
        DWP dwb{cw_r + blk * DI * KC, cb_r + blk * DI, xc1, 1};
        k_dwconv<<<dim3(gXC, 1, 2), TPB>>>(xz, dwa, dwb);

        GP xa{xc0, xp_f + (size_t)blk * XD * DI, nullptr, xd0};
        GP xb{xc1, xp_r + (size_t)blk * XD * DI, nullptr, xd1};
        k_gemm<<<dim3(1, BL / 128, 2), TPB>>>(xa, xb, DI, DI, XD, XD);

        SCP sa{xc0, xd0, dtw_f + blk * DI * DTR, dtb_f + blk * DI,
               Al_f + (size_t)blk * DI * DS, D_f + blk * DI, y0};
        SCP sb{xc1, xd1, dtw_r + blk * DI * DTR, dtb_r + blk * DI,
               Al_r + (size_t)blk * DI * DS, D_r + blk * DI, y1};
        k_scan<<<dim3(DI / 32, B_, 2), TPB>>>(sa, sb);

        float* dst = (blk == 1) ? out : ht;
        k_gemm_out<<<dim3(1, BL / 128, 1), TPB>>>(
            y0, y1, xz, opw + (size_t)blk * E_ * DI, ht, dst);
    }
}